// round 12
// baseline (speedup 1.0000x reference)
#include <cuda_runtime.h>
#include <cuda_bf16.h>
#include <cstdint>

#define N_ROWS 8192
#define DIM    512
#define INV_T  (1.0f / 0.07f)

#define TM 256                    // CTA rows
#define TN 128                    // CTA cols
#define KC 64
#define NK (DIM / KC)             // 8 K-chunks
#define NTC (N_ROWS / 256)        // 32 coarse tile-rows
#define NCOARSE (NTC * (NTC + 1) / 2)   // 528 coarse tiles
#define NCTA (NCOARSE * 2)              // 1056 CTAs
#define STAGE_BYTES ((TM + TN) * KC * 2)   // 48 KB
#define NSTAGE 3
#define SMEM_DYN (NSTAGE * STAGE_BYTES)    // 144 KB

// ---------------- scratch (no allocs allowed) ----------------
__device__ __align__(16) __nv_bfloat16 g_Hn[N_ROWS * DIM];   // normalized, bf16, row-major
__device__ float g_total[N_ROWS];
__device__ float g_pos[N_ROWS];
__device__ int   g_hist[128];
__device__ int   g_lab[N_ROWS];

// ---------------- prep: zero everything + label dtype detect + decode ----------------
__global__ void k_prep(const void* labels, float* out) {
    __shared__ int s_is64;
    int i = blockIdx.x * blockDim.x + threadIdx.x;
    if (threadIdx.x == 0) {
        const int* l32 = (const int*)labels;
        int odd_nonzero = 0;
        for (int q = 0; q < 32; q++)
            if (l32[2 * q + 1] != 0) odd_nonzero++;
        s_is64 = (odd_nonzero == 0) ? 1 : 0;
    }
    __syncthreads();
    if (i == 0) out[0] = 0.f;
    if (i < 128) g_hist[i] = 0;
    if (i < N_ROWS) {
        g_total[i] = 0.f;
        g_pos[i]   = 0.f;
        int l = s_is64 ? (int)((const long long*)labels)[i]
                       : ((const int*)labels)[i];
        g_lab[i] = l & 127;
    }
}

// ---------------- L2-normalize rows (bf16 out) + global histogram ----------------
__global__ void k_normalize(const float* __restrict__ hidden) {
    int row = blockIdx.x;
    if (threadIdx.x == 0) atomicAdd(&g_hist[g_lab[row]], 1);
    const float4* src = reinterpret_cast<const float4*>(hidden + (size_t)row * DIM);
    float4 v = src[threadIdx.x];
    float ss = v.x * v.x + v.y * v.y + v.z * v.z + v.w * v.w;
    #pragma unroll
    for (int o = 16; o; o >>= 1) ss += __shfl_xor_sync(~0u, ss, o);
    __shared__ float s[4];
    if ((threadIdx.x & 31) == 0) s[threadIdx.x >> 5] = ss;
    __syncthreads();
    float tot = s[0] + s[1] + s[2] + s[3];
    float inv = 1.0f / fmaxf(sqrtf(tot), 1e-12f);
    __nv_bfloat162 p0 = __floats2bfloat162_rn(v.x * inv, v.y * inv);
    __nv_bfloat162 p1 = __floats2bfloat162_rn(v.z * inv, v.w * inv);
    uint2 pk;
    pk.x = *reinterpret_cast<uint32_t*>(&p0);
    pk.y = *reinterpret_cast<uint32_t*>(&p1);
    *reinterpret_cast<uint2*>((char*)g_Hn + (size_t)row * DIM * 2 + threadIdx.x * 8) = pk;
}

__device__ __forceinline__ uint32_t smem_u32(const void* p) {
    return (uint32_t)__cvta_generic_to_shared(p);
}
__device__ __forceinline__ void cp16(uint32_t dst, const void* src) {
    asm volatile("cp.async.cg.shared.global [%0], [%1], 16;" :: "r"(dst), "l"(src) : "memory");
}

// ---------------- symmetric-tile GEMM + fused epilogue, 256x128 CTA tile ----------------
// Coarse 256x256 upper triangle; each coarse tile = 2 CTAs (col halves).
// Off-diag coarse: row-scatter + col-scatter. Diag coarse: full block both
// orders -> row-scatter only (each unordered pair appears in both orders).
__global__ void __launch_bounds__(256, 1) k_gemm_sym() {
    extern __shared__ char smem[];
    __shared__ float s_colT[TN], s_colP[TN];
    __shared__ int   s_labI[TM], s_labJ[TN];

    const int tid  = threadIdx.x;
    const int lane = tid & 31, warp = tid >> 5;
    const int wm = warp >> 1, wn = warp & 1;   // 4x2 warps, warp tile 64x64

    // decode coarse upper-triangle tile (ti <= tj) over NTC=32
    int c = blockIdx.x >> 1;
    int h = blockIdx.x & 1;
    int ti = (int)((65.0f - sqrtf(65.0f * 65.0f - 8.0f * (float)c)) * 0.5f);
    #define FOFF(t) ((t) * (2 * NTC + 1 - (t)) / 2)
    while (FOFF(ti + 1) <= c) ti++;
    while (FOFF(ti) > c) ti--;
    int tj = ti + (c - FOFF(ti));
    const int i0 = ti * 256, j0 = tj * 256 + h * TN;
    const bool diag = (ti == tj);

    if (tid < TN) { s_colT[tid] = 0.f; s_colP[tid] = 0.f; s_labJ[tid] = g_lab[j0 + tid]; }
    s_labI[tid] = g_lab[i0 + tid];

    // ---- cp.async tile loader: A 256 rows, B 128 rows x 8 x 16B, XOR-swizzled ----
    auto load_stage = [&](int s, int k) {
        char* dA = smem + s * STAGE_BYTES;
        char* dB = dA + TM * 128;
        const char* gA = (const char*)g_Hn + ((size_t)i0 * DIM + k * KC) * 2;
        const char* gB = (const char*)g_Hn + ((size_t)j0 * DIM + k * KC) * 2;
        #pragma unroll
        for (int u = 0; u < 8; u++) {
            int q = tid + u * 256;           // 0..2047
            int r = q >> 3, cc = q & 7;
            uint32_t sw = (uint32_t)((cc ^ (r & 7)) << 4);
            cp16(smem_u32(dA + r * 128 + sw), gA + (size_t)r * (DIM * 2) + cc * 16);
        }
        #pragma unroll
        for (int u = 0; u < 4; u++) {
            int q = tid + u * 256;           // 0..1023
            int r = q >> 3, cc = q & 7;
            uint32_t sw = (uint32_t)((cc ^ (r & 7)) << 4);
            cp16(smem_u32(dB + r * 128 + sw), gB + (size_t)r * (DIM * 2) + cc * 16);
        }
    };

    load_stage(0, 0);
    asm volatile("cp.async.commit_group;" ::: "memory");
    load_stage(1, 1);
    asm volatile("cp.async.commit_group;" ::: "memory");

    float acc[4][8][4];
    #pragma unroll
    for (int mi = 0; mi < 4; mi++)
        #pragma unroll
        for (int ni = 0; ni < 8; ni++)
            #pragma unroll
            for (int e = 0; e < 4; e++) acc[mi][ni][e] = 0.f;

    for (int k = 0; k < NK; k++) {
        __syncthreads();                          // all warps done with buf[(k+2)%3]
        if (k + 2 < NK) load_stage((k + 2) % NSTAGE, k + 2);
        asm volatile("cp.async.commit_group;" ::: "memory");
        asm volatile("cp.async.wait_group 2;" ::: "memory");
        __syncthreads();                          // stage k visible

        char* A = smem + (k % NSTAGE) * STAGE_BYTES;
        char* B = A + TM * 128;
        #pragma unroll
        for (int ks = 0; ks < 4; ks++) {          // 4 x k16
            uint32_t a[4][4];
            #pragma unroll
            for (int mi = 0; mi < 4; mi++) {
                int r = wm * 64 + mi * 16 + (lane & 15);
                int ch = ks * 2 + (lane >> 4);
                uint32_t addr = smem_u32(A + r * 128 + ((ch ^ (r & 7)) << 4));
                asm volatile("ldmatrix.sync.aligned.m8n8.x4.shared.b16 {%0,%1,%2,%3}, [%4];\n"
                    : "=r"(a[mi][0]), "=r"(a[mi][1]), "=r"(a[mi][2]), "=r"(a[mi][3])
                    : "r"(addr));
            }
            uint32_t b[8][2];
            #pragma unroll
            for (int nb = 0; nb < 4; nb++) {
                int r = wn * 64 + nb * 16 + (lane >> 4) * 8 + (lane & 7);
                int ch = ks * 2 + ((lane >> 3) & 1);
                uint32_t addr = smem_u32(B + r * 128 + ((ch ^ (r & 7)) << 4));
                asm volatile("ldmatrix.sync.aligned.m8n8.x4.shared.b16 {%0,%1,%2,%3}, [%4];\n"
                    : "=r"(b[2 * nb][0]), "=r"(b[2 * nb][1]),
                      "=r"(b[2 * nb + 1][0]), "=r"(b[2 * nb + 1][1])
                    : "r"(addr));
            }
            #pragma unroll
            for (int mi = 0; mi < 4; mi++)
                #pragma unroll
                for (int ni = 0; ni < 8; ni++)
                    asm volatile(
                        "mma.sync.aligned.m16n8k16.row.col.f32.bf16.bf16.f32 "
                        "{%0,%1,%2,%3},{%4,%5,%6,%7},{%8,%9},{%0,%1,%2,%3};\n"
                        : "+f"(acc[mi][ni][0]), "+f"(acc[mi][ni][1]),
                          "+f"(acc[mi][ni][2]), "+f"(acc[mi][ni][3])
                        : "r"(a[mi][0]), "r"(a[mi][1]), "r"(a[mi][2]), "r"(a[mi][3]),
                          "r"(b[ni][0]), "r"(b[ni][1]));
        }
    }
    __syncthreads();

    // ---- epilogue: exp once, scatter to row sums (i) and column sums (j) ----
    float colT[16], colP[16];
    #pragma unroll
    for (int x = 0; x < 16; x++) { colT[x] = 0.f; colP[x] = 0.f; }

    #pragma unroll
    for (int mi = 0; mi < 4; mi++) {
        #pragma unroll
        for (int v = 0; v < 2; v++) {
            const int rl = wm * 64 + mi * 16 + (lane >> 2) + v * 8;
            const int gi = i0 + rl;
            const int li = s_labI[rl];
            float sT = 0.f, sP = 0.f;
            #pragma unroll
            for (int ni = 0; ni < 8; ni++) {
                #pragma unroll
                for (int e = 0; e < 2; e++) {
                    const int cl = wn * 64 + ni * 8 + (lane & 3) * 2 + e;
                    float ev = __expf(acc[mi][ni][v * 2 + e] * INV_T);
                    bool same = (s_labJ[cl] == li);
                    if (!(diag && (j0 + cl) == gi)) {
                        sT += ev;
                        if (same) sP += ev;
                        if (!diag) {
                            colT[ni * 2 + e] += ev;
                            if (same) colP[ni * 2 + e] += ev;
                        }
                    }
                }
            }
            sT += __shfl_xor_sync(~0u, sT, 1); sP += __shfl_xor_sync(~0u, sP, 1);
            sT += __shfl_xor_sync(~0u, sT, 2); sP += __shfl_xor_sync(~0u, sP, 2);
            if ((lane & 3) == 0) {
                atomicAdd(&g_total[gi], sT);
                atomicAdd(&g_pos[gi], sP);
            }
        }
    }

    if (!diag) {
        #pragma unroll
        for (int x = 0; x < 16; x++) {
            float cT = colT[x], cP = colP[x];
            cT += __shfl_xor_sync(~0u, cT, 4);  cP += __shfl_xor_sync(~0u, cP, 4);
            cT += __shfl_xor_sync(~0u, cT, 8);  cP += __shfl_xor_sync(~0u, cP, 8);
            cT += __shfl_xor_sync(~0u, cT, 16); cP += __shfl_xor_sync(~0u, cP, 16);
            if (lane < 4) {
                int cl = wn * 64 + (x >> 1) * 8 + lane * 2 + (x & 1);
                atomicAdd(&s_colT[cl], cT);
                atomicAdd(&s_colP[cl], cP);
            }
        }
        __syncthreads();
        if (tid < TN) {
            atomicAdd(&g_total[j0 + tid], s_colT[tid]);
            atomicAdd(&g_pos[j0 + tid], s_colP[tid]);
        }
    }
}

// ---------------- final reduction: 32 blocks, one row per thread ----------------
__global__ void k_finalize(float* out) {
    int i = blockIdx.x * blockDim.x + threadIdx.x;
    float tot = g_total[i] + expf(INV_T);           // exact diagonal term
    float cnt = (float)(g_hist[g_lab[i]] - 1);
    float ps  = g_pos[i] / (cnt + 1e-9f);
    float s   = logf(ps / tot) * (-1.0f / (float)N_ROWS);
    #pragma unroll
    for (int o = 16; o; o >>= 1) s += __shfl_xor_sync(~0u, s, o);
    __shared__ float red[8];
    if ((threadIdx.x & 31) == 0) red[threadIdx.x >> 5] = s;
    __syncthreads();
    if (threadIdx.x < 8) {
        float v = red[threadIdx.x];
        #pragma unroll
        for (int o = 4; o; o >>= 1) v += __shfl_xor_sync(0xFF, v, o);
        if (threadIdx.x == 0) atomicAdd(out, v);
    }
}

extern "C" void kernel_launch(void* const* d_in, const int* in_sizes, int n_in,
                              void* d_out, int out_size) {
    const float* hidden = (const float*)d_in[0];
    const void*  labels = d_in[1];

    cudaFuncSetAttribute(k_gemm_sym, cudaFuncAttributeMaxDynamicSharedMemorySize, SMEM_DYN);

    k_prep<<<32, 256>>>(labels, (float*)d_out);
    k_normalize<<<N_ROWS, 128>>>(hidden);
    k_gemm_sym<<<NCTA, 256, SMEM_DYN>>>();
    k_finalize<<<32, 256>>>((float*)d_out);
}

// round 14
// speedup vs baseline: 1.1522x; 1.1522x over previous
#include <cuda_runtime.h>
#include <cuda_bf16.h>
#include <cstdint>

#define N_ROWS 8192
#define DIM    512
#define INV_T  (1.0f / 0.07f)

#define TM 128                    // CTA rows
#define TN 64                     // CTA cols
#define KC 64
#define NK (DIM / KC)             // 8 K-chunks
#define NTC (N_ROWS / 128)        // 64 coarse tile-rows (128x128 coarse)
#define NCOARSE (NTC * (NTC + 1) / 2)   // 2080 coarse tiles
#define NCTA (NCOARSE * 2)              // 4160 CTAs (2 col halves)
#define STAGE_BYTES ((TM + TN) * KC * 2)   // 24 KB
#define NSTAGE 3
#define SMEM_DYN (NSTAGE * STAGE_BYTES)    // 72 KB -> 3 CTAs/SM

// ---------------- scratch (no allocs allowed) ----------------
__device__ __align__(16) __nv_bfloat16 g_Hn[N_ROWS * DIM];   // normalized, bf16, row-major
__device__ float g_total[N_ROWS];
__device__ float g_pos[N_ROWS];
__device__ int   g_hist[128];
__device__ int   g_lab[N_ROWS];

// ---------------- prep: zero everything + label dtype detect + decode ----------------
__global__ void k_prep(const void* labels, float* out) {
    __shared__ int s_is64;
    int i = blockIdx.x * blockDim.x + threadIdx.x;
    if (threadIdx.x == 0) {
        const int* l32 = (const int*)labels;
        int odd_nonzero = 0;
        for (int q = 0; q < 32; q++)
            if (l32[2 * q + 1] != 0) odd_nonzero++;
        s_is64 = (odd_nonzero == 0) ? 1 : 0;
    }
    __syncthreads();
    if (i == 0) out[0] = 0.f;
    if (i < 128) g_hist[i] = 0;
    if (i < N_ROWS) {
        g_total[i] = 0.f;
        g_pos[i]   = 0.f;
        int l = s_is64 ? (int)((const long long*)labels)[i]
                       : ((const int*)labels)[i];
        g_lab[i] = l & 127;
    }
}

// ---------------- L2-normalize rows (bf16 out) + global histogram ----------------
__global__ void k_normalize(const float* __restrict__ hidden) {
    int row = blockIdx.x;
    if (threadIdx.x == 0) atomicAdd(&g_hist[g_lab[row]], 1);
    const float4* src = reinterpret_cast<const float4*>(hidden + (size_t)row * DIM);
    float4 v = src[threadIdx.x];
    float ss = v.x * v.x + v.y * v.y + v.z * v.z + v.w * v.w;
    #pragma unroll
    for (int o = 16; o; o >>= 1) ss += __shfl_xor_sync(~0u, ss, o);
    __shared__ float s[4];
    if ((threadIdx.x & 31) == 0) s[threadIdx.x >> 5] = ss;
    __syncthreads();
    float tot = s[0] + s[1] + s[2] + s[3];
    float inv = 1.0f / fmaxf(sqrtf(tot), 1e-12f);
    __nv_bfloat162 p0 = __floats2bfloat162_rn(v.x * inv, v.y * inv);
    __nv_bfloat162 p1 = __floats2bfloat162_rn(v.z * inv, v.w * inv);
    uint2 pk;
    pk.x = *reinterpret_cast<uint32_t*>(&p0);
    pk.y = *reinterpret_cast<uint32_t*>(&p1);
    *reinterpret_cast<uint2*>((char*)g_Hn + (size_t)row * DIM * 2 + threadIdx.x * 8) = pk;
}

__device__ __forceinline__ uint32_t smem_u32(const void* p) {
    return (uint32_t)__cvta_generic_to_shared(p);
}
__device__ __forceinline__ void cp16(uint32_t dst, const void* src) {
    asm volatile("cp.async.cg.shared.global [%0], [%1], 16;" :: "r"(dst), "l"(src) : "memory");
}

// ---------------- symmetric-tile GEMM + fused epilogue, 128x64 CTA tile, 3 CTA/SM ----------------
// Coarse 128x128 upper triangle; each coarse tile = 2 CTAs (col halves of 64).
// Off-diag coarse: row-scatter + col-scatter. Diag coarse: full block (both
// halves, both orders of each pair) -> row-scatter only, skip i==j elements.
__global__ void __launch_bounds__(256, 3) k_gemm_sym() {
    extern __shared__ char smem[];
    __shared__ float s_colT[TN], s_colP[TN];
    __shared__ int   s_labI[TM], s_labJ[TN];

    const int tid  = threadIdx.x;
    const int lane = tid & 31, warp = tid >> 5;
    const int wm = warp >> 1, wn = warp & 1;   // 4x2 warps, warp tile 32x32

    // decode coarse upper-triangle tile (ti <= tj) over NTC=64
    int c = blockIdx.x >> 1;
    int h = blockIdx.x & 1;
    int ti = (int)((129.0f - sqrtf(129.0f * 129.0f - 8.0f * (float)c)) * 0.5f);
    #define FOFF(t) ((t) * (2 * NTC + 1 - (t)) / 2)
    while (FOFF(ti + 1) <= c) ti++;
    while (FOFF(ti) > c) ti--;
    int tj = ti + (c - FOFF(ti));
    const int i0 = ti * 128, j0 = tj * 128 + h * TN;
    const bool diag = (ti == tj);

    if (tid < TN) { s_colT[tid] = 0.f; s_colP[tid] = 0.f; s_labJ[tid] = g_lab[j0 + tid]; }
    if (tid < TM) s_labI[tid] = g_lab[i0 + tid];

    // ---- cp.async tile loader: A 128 rows + B 64 rows, 8 x 16B each, XOR-swizzled ----
    auto load_stage = [&](int s, int k) {
        char* dA = smem + s * STAGE_BYTES;
        char* dB = dA + TM * 128;
        const char* gA = (const char*)g_Hn + ((size_t)i0 * DIM + k * KC) * 2;
        const char* gB = (const char*)g_Hn + ((size_t)j0 * DIM + k * KC) * 2;
        #pragma unroll
        for (int u = 0; u < 4; u++) {
            int q = tid + u * 256;           // 0..1023
            int r = q >> 3, cc = q & 7;
            uint32_t sw = (uint32_t)((cc ^ (r & 7)) << 4);
            cp16(smem_u32(dA + r * 128 + sw), gA + (size_t)r * (DIM * 2) + cc * 16);
        }
        #pragma unroll
        for (int u = 0; u < 2; u++) {
            int q = tid + u * 256;           // 0..511
            int r = q >> 3, cc = q & 7;
            uint32_t sw = (uint32_t)((cc ^ (r & 7)) << 4);
            cp16(smem_u32(dB + r * 128 + sw), gB + (size_t)r * (DIM * 2) + cc * 16);
        }
    };

    load_stage(0, 0);
    asm volatile("cp.async.commit_group;" ::: "memory");
    load_stage(1, 1);
    asm volatile("cp.async.commit_group;" ::: "memory");

    float acc[2][4][4];
    #pragma unroll
    for (int mi = 0; mi < 2; mi++)
        #pragma unroll
        for (int ni = 0; ni < 4; ni++)
            #pragma unroll
            for (int e = 0; e < 4; e++) acc[mi][ni][e] = 0.f;

    for (int k = 0; k < NK; k++) {
        __syncthreads();                          // all warps done with buf[(k+2)%3]
        if (k + 2 < NK) load_stage((k + 2) % NSTAGE, k + 2);
        asm volatile("cp.async.commit_group;" ::: "memory");
        asm volatile("cp.async.wait_group 2;" ::: "memory");
        __syncthreads();                          // stage k visible

        char* A = smem + (k % NSTAGE) * STAGE_BYTES;
        char* B = A + TM * 128;
        #pragma unroll
        for (int ks = 0; ks < 4; ks++) {          // 4 x k16
            uint32_t a[2][4];
            #pragma unroll
            for (int mi = 0; mi < 2; mi++) {
                int r = wm * 32 + mi * 16 + (lane & 15);
                int ch = ks * 2 + (lane >> 4);
                uint32_t addr = smem_u32(A + r * 128 + ((ch ^ (r & 7)) << 4));
                asm volatile("ldmatrix.sync.aligned.m8n8.x4.shared.b16 {%0,%1,%2,%3}, [%4];\n"
                    : "=r"(a[mi][0]), "=r"(a[mi][1]), "=r"(a[mi][2]), "=r"(a[mi][3])
                    : "r"(addr));
            }
            uint32_t b[4][2];
            #pragma unroll
            for (int nb = 0; nb < 2; nb++) {
                int r = wn * 32 + nb * 16 + (lane >> 4) * 8 + (lane & 7);
                int ch = ks * 2 + ((lane >> 3) & 1);
                uint32_t addr = smem_u32(B + r * 128 + ((ch ^ (r & 7)) << 4));
                asm volatile("ldmatrix.sync.aligned.m8n8.x4.shared.b16 {%0,%1,%2,%3}, [%4];\n"
                    : "=r"(b[2 * nb][0]), "=r"(b[2 * nb][1]),
                      "=r"(b[2 * nb + 1][0]), "=r"(b[2 * nb + 1][1])
                    : "r"(addr));
            }
            #pragma unroll
            for (int mi = 0; mi < 2; mi++)
                #pragma unroll
                for (int ni = 0; ni < 4; ni++)
                    asm volatile(
                        "mma.sync.aligned.m16n8k16.row.col.f32.bf16.bf16.f32 "
                        "{%0,%1,%2,%3},{%4,%5,%6,%7},{%8,%9},{%0,%1,%2,%3};\n"
                        : "+f"(acc[mi][ni][0]), "+f"(acc[mi][ni][1]),
                          "+f"(acc[mi][ni][2]), "+f"(acc[mi][ni][3])
                        : "r"(a[mi][0]), "r"(a[mi][1]), "r"(a[mi][2]), "r"(a[mi][3]),
                          "r"(b[ni][0]), "r"(b[ni][1]));
        }
    }
    __syncthreads();

    // ---- epilogue: exp once, scatter to row sums (i) and column sums (j) ----
    float colT[8], colP[8];
    #pragma unroll
    for (int x = 0; x < 8; x++) { colT[x] = 0.f; colP[x] = 0.f; }

    #pragma unroll
    for (int mi = 0; mi < 2; mi++) {
        #pragma unroll
        for (int v = 0; v < 2; v++) {
            const int rl = wm * 32 + mi * 16 + (lane >> 2) + v * 8;
            const int gi = i0 + rl;
            const int li = s_labI[rl];
            float sT = 0.f, sP = 0.f;
            #pragma unroll
            for (int ni = 0; ni < 4; ni++) {
                #pragma unroll
                for (int e = 0; e < 2; e++) {
                    const int cl = wn * 32 + ni * 8 + (lane & 3) * 2 + e;
                    float ev = __expf(acc[mi][ni][v * 2 + e] * INV_T);
                    bool same = (s_labJ[cl] == li);
                    if (!(diag && (j0 + cl) == gi)) {
                        sT += ev;
                        if (same) sP += ev;
                        if (!diag) {
                            colT[ni * 2 + e] += ev;
                            if (same) colP[ni * 2 + e] += ev;
                        }
                    }
                }
            }
            sT += __shfl_xor_sync(~0u, sT, 1); sP += __shfl_xor_sync(~0u, sP, 1);
            sT += __shfl_xor_sync(~0u, sT, 2); sP += __shfl_xor_sync(~0u, sP, 2);
            if ((lane & 3) == 0) {
                atomicAdd(&g_total[gi], sT);
                atomicAdd(&g_pos[gi], sP);
            }
        }
    }

    if (!diag) {
        #pragma unroll
        for (int x = 0; x < 8; x++) {
            float cT = colT[x], cP = colP[x];
            cT += __shfl_xor_sync(~0u, cT, 4);  cP += __shfl_xor_sync(~0u, cP, 4);
            cT += __shfl_xor_sync(~0u, cT, 8);  cP += __shfl_xor_sync(~0u, cP, 8);
            cT += __shfl_xor_sync(~0u, cT, 16); cP += __shfl_xor_sync(~0u, cP, 16);
            if (lane < 4) {
                int cl = wn * 32 + (x >> 1) * 8 + lane * 2 + (x & 1);
                atomicAdd(&s_colT[cl], cT);
                atomicAdd(&s_colP[cl], cP);
            }
        }
        __syncthreads();
        if (tid < TN) {
            atomicAdd(&g_total[j0 + tid], s_colT[tid]);
            atomicAdd(&g_pos[j0 + tid], s_colP[tid]);
        }
    }
}

// ---------------- final reduction: 32 blocks, one row per thread ----------------
__global__ void k_finalize(float* out) {
    int i = blockIdx.x * blockDim.x + threadIdx.x;
    float tot = g_total[i] + expf(INV_T);           // exact diagonal term
    float cnt = (float)(g_hist[g_lab[i]] - 1);
    float ps  = g_pos[i] / (cnt + 1e-9f);
    float s   = logf(ps / tot) * (-1.0f / (float)N_ROWS);
    #pragma unroll
    for (int o = 16; o; o >>= 1) s += __shfl_xor_sync(~0u, s, o);
    __shared__ float red[8];
    if ((threadIdx.x & 31) == 0) red[threadIdx.x >> 5] = s;
    __syncthreads();
    if (threadIdx.x < 8) {
        float v = red[threadIdx.x];
        #pragma unroll
        for (int o = 4; o; o >>= 1) v += __shfl_xor_sync(0xFF, v, o);
        if (threadIdx.x == 0) atomicAdd(out, v);
    }
}

extern "C" void kernel_launch(void* const* d_in, const int* in_sizes, int n_in,
                              void* d_out, int out_size) {
    const float* hidden = (const float*)d_in[0];
    const void*  labels = d_in[1];

    cudaFuncSetAttribute(k_gemm_sym, cudaFuncAttributeMaxDynamicSharedMemorySize, SMEM_DYN);

    k_prep<<<32, 256>>>(labels, (float*)d_out);
    k_normalize<<<N_ROWS, 128>>>(hidden);
    k_gemm_sym<<<NCTA, 256, SMEM_DYN>>>();
    k_finalize<<<32, 256>>>((float*)d_out);
}

// round 15
// speedup vs baseline: 1.2500x; 1.0849x over previous
#include <cuda_runtime.h>
#include <cuda_bf16.h>
#include <cstdint>

#define N_ROWS 8192
#define DIM    512
#define INV_T  (1.0f / 0.07f)

#define TM 128
#define TN 128
#define KC 64
#define NK (DIM / KC)            // 8 K-chunks
#define NTI (N_ROWS / TM)        // 64 tile-rows
#define NTILE (NTI * (NTI + 1) / 2)   // 2080 upper-triangle tiles
#define STAGE_BYTES ((TM + TN) * KC * 2)   // 32 KB
#define NSTAGE 3
#define SMEM_DYN (NSTAGE * STAGE_BYTES)    // 96 KB

// ---------------- scratch (no allocs allowed; zero-init at module load) ----------------
__device__ __align__(16) __nv_bfloat16 g_Hn[N_ROWS * DIM];   // normalized, bf16, row-major
__device__ float    g_total[N_ROWS];
__device__ float    g_pos[N_ROWS];
__device__ int      g_hist[128];      // zero at load; re-zeroed by k_finalize each call
__device__ int      g_lab[N_ROWS];
__device__ float    g_part[32];
__device__ unsigned g_done;           // zero at load; reset by k_finalize each call

// ---------------- L2-normalize rows (bf16 out) + fused prep ----------------
// Per row-block: decode own label (dtype-sniffed), zero own accumulators,
// histogram atomic. g_hist arrives zeroed (module load / previous finalize).
__global__ void k_normalize(const float* __restrict__ hidden, const void* labels) {
    int row = blockIdx.x;
    if (threadIdx.x == 0) {
        const int* l32 = (const int*)labels;
        int odd_nonzero = 0;
        #pragma unroll
        for (int q = 0; q < 32; q++)
            if (l32[2 * q + 1] != 0) odd_nonzero++;
        int l = (odd_nonzero == 0) ? (int)((const long long*)labels)[row]
                                   : l32[row];
        l &= 127;
        g_lab[row]   = l;
        g_total[row] = 0.f;
        g_pos[row]   = 0.f;
        atomicAdd(&g_hist[l], 1);
    }
    const float4* src = reinterpret_cast<const float4*>(hidden + (size_t)row * DIM);
    float4 v = src[threadIdx.x];
    float ss = v.x * v.x + v.y * v.y + v.z * v.z + v.w * v.w;
    #pragma unroll
    for (int o = 16; o; o >>= 1) ss += __shfl_xor_sync(~0u, ss, o);
    __shared__ float s[4];
    if ((threadIdx.x & 31) == 0) s[threadIdx.x >> 5] = ss;
    __syncthreads();
    float tot = s[0] + s[1] + s[2] + s[3];
    float inv = 1.0f / fmaxf(sqrtf(tot), 1e-12f);
    __nv_bfloat162 p0 = __floats2bfloat162_rn(v.x * inv, v.y * inv);
    __nv_bfloat162 p1 = __floats2bfloat162_rn(v.z * inv, v.w * inv);
    uint2 pk;
    pk.x = *reinterpret_cast<uint32_t*>(&p0);
    pk.y = *reinterpret_cast<uint32_t*>(&p1);
    *reinterpret_cast<uint2*>((char*)g_Hn + (size_t)row * DIM * 2 + threadIdx.x * 8) = pk;
}

__device__ __forceinline__ uint32_t smem_u32(const void* p) {
    return (uint32_t)__cvta_generic_to_shared(p);
}
__device__ __forceinline__ void cp16(uint32_t dst, const void* src) {
    asm volatile("cp.async.cg.shared.global [%0], [%1], 16;" :: "r"(dst), "l"(src) : "memory");
}

// ---------------- symmetric-tile GEMM + fused epilogue (R11 measured-best, unchanged) ----------------
__global__ void __launch_bounds__(256, 2) k_gemm_sym() {
    extern __shared__ char smem[];
    __shared__ float s_colT[TN], s_colP[TN];
    __shared__ int   s_labI[TM], s_labJ[TN];

    const int tid  = threadIdx.x;
    const int lane = tid & 31, warp = tid >> 5;
    const int wm = warp >> 1, wn = warp & 1;   // 4x2 warps over 128x128

    // decode upper-triangle tile (ti <= tj); offset f(t) = t*(2*NTI+1-t)/2
    int bid = blockIdx.x;
    int ti = (int)((129.0f - sqrtf(129.0f * 129.0f - 8.0f * (float)bid)) * 0.5f);
    #define FOFF(t) ((t) * (2 * NTI + 1 - (t)) / 2)
    while (FOFF(ti + 1) <= bid) ti++;
    while (FOFF(ti) > bid) ti--;
    int tj = ti + (bid - FOFF(ti));
    const int i0 = ti * TM, j0 = tj * TN;
    const bool diag = (ti == tj);

    if (tid < TM) {
        s_labI[tid] = g_lab[i0 + tid];
        s_labJ[tid] = g_lab[j0 + tid];
        s_colT[tid] = 0.f; s_colP[tid] = 0.f;
    }

    // ---- cp.async tile loader: 128 rows x 8 x 16B per operand, XOR-swizzled ----
    auto load_stage = [&](int s, int k) {
        char* dA = smem + s * STAGE_BYTES;
        char* dB = dA + TM * KC * 2;
        const char* gA = (const char*)g_Hn + ((size_t)i0 * DIM + k * KC) * 2;
        const char* gB = (const char*)g_Hn + ((size_t)j0 * DIM + k * KC) * 2;
        #pragma unroll
        for (int u = 0; u < 4; u++) {
            int q = tid + u * 256;           // 0..1023
            int r = q >> 3, c = q & 7;
            uint32_t sw = (uint32_t)((c ^ (r & 7)) << 4);
            cp16(smem_u32(dA + r * 128 + sw), gA + (size_t)r * (DIM * 2) + c * 16);
            cp16(smem_u32(dB + r * 128 + sw), gB + (size_t)r * (DIM * 2) + c * 16);
        }
    };

    load_stage(0, 0);
    asm volatile("cp.async.commit_group;" ::: "memory");
    load_stage(1, 1);
    asm volatile("cp.async.commit_group;" ::: "memory");

    float acc[2][8][4];
    #pragma unroll
    for (int mi = 0; mi < 2; mi++)
        #pragma unroll
        for (int ni = 0; ni < 8; ni++)
            #pragma unroll
            for (int e = 0; e < 4; e++) acc[mi][ni][e] = 0.f;

    for (int k = 0; k < NK; k++) {
        __syncthreads();                          // all warps done with buf[(k+2)%3]
        if (k + 2 < NK) load_stage((k + 2) % NSTAGE, k + 2);
        asm volatile("cp.async.commit_group;" ::: "memory");
        asm volatile("cp.async.wait_group 2;" ::: "memory");
        __syncthreads();                          // stage k visible

        char* A = smem + (k % NSTAGE) * STAGE_BYTES;
        char* B = A + TM * KC * 2;
        #pragma unroll
        for (int ks = 0; ks < 4; ks++) {          // 4 x k16
            uint32_t a[2][4];
            #pragma unroll
            for (int mi = 0; mi < 2; mi++) {
                int r = wm * 32 + mi * 16 + (lane & 15);
                int ch = ks * 2 + (lane >> 4);
                uint32_t addr = smem_u32(A + r * 128 + ((ch ^ (r & 7)) << 4));
                asm volatile("ldmatrix.sync.aligned.m8n8.x4.shared.b16 {%0,%1,%2,%3}, [%4];\n"
                    : "=r"(a[mi][0]), "=r"(a[mi][1]), "=r"(a[mi][2]), "=r"(a[mi][3])
                    : "r"(addr));
            }
            uint32_t b[8][2];
            #pragma unroll
            for (int nb = 0; nb < 4; nb++) {
                int r = wn * 64 + nb * 16 + (lane >> 4) * 8 + (lane & 7);
                int ch = ks * 2 + ((lane >> 3) & 1);
                uint32_t addr = smem_u32(B + r * 128 + ((ch ^ (r & 7)) << 4));
                asm volatile("ldmatrix.sync.aligned.m8n8.x4.shared.b16 {%0,%1,%2,%3}, [%4];\n"
                    : "=r"(b[2 * nb][0]), "=r"(b[2 * nb][1]),
                      "=r"(b[2 * nb + 1][0]), "=r"(b[2 * nb + 1][1])
                    : "r"(addr));
            }
            #pragma unroll
            for (int mi = 0; mi < 2; mi++)
                #pragma unroll
                for (int ni = 0; ni < 8; ni++)
                    asm volatile(
                        "mma.sync.aligned.m16n8k16.row.col.f32.bf16.bf16.f32 "
                        "{%0,%1,%2,%3},{%4,%5,%6,%7},{%8,%9},{%0,%1,%2,%3};\n"
                        : "+f"(acc[mi][ni][0]), "+f"(acc[mi][ni][1]),
                          "+f"(acc[mi][ni][2]), "+f"(acc[mi][ni][3])
                        : "r"(a[mi][0]), "r"(a[mi][1]), "r"(a[mi][2]), "r"(a[mi][3]),
                          "r"(b[ni][0]), "r"(b[ni][1]));
        }
    }
    __syncthreads();

    // ---- epilogue: exp once, scatter to row sums (i) and column sums (j) ----
    float colT[16], colP[16];
    #pragma unroll
    for (int x = 0; x < 16; x++) { colT[x] = 0.f; colP[x] = 0.f; }

    #pragma unroll
    for (int mi = 0; mi < 2; mi++) {
        #pragma unroll
        for (int v = 0; v < 2; v++) {
            const int rl = wm * 32 + mi * 16 + (lane >> 2) + v * 8;
            const int li = s_labI[rl];
            float sT = 0.f, sP = 0.f;
            #pragma unroll
            for (int ni = 0; ni < 8; ni++) {
                #pragma unroll
                for (int e = 0; e < 2; e++) {
                    const int cl = wn * 64 + ni * 8 + (lane & 3) * 2 + e;
                    float ev = __expf(acc[mi][ni][v * 2 + e] * INV_T);
                    bool same = (s_labJ[cl] == li);
                    if (!(diag && rl == cl)) {
                        sT += ev;
                        if (same) sP += ev;
                        if (!diag) {
                            colT[ni * 2 + e] += ev;
                            if (same) colP[ni * 2 + e] += ev;
                        }
                    }
                }
            }
            sT += __shfl_xor_sync(~0u, sT, 1); sP += __shfl_xor_sync(~0u, sP, 1);
            sT += __shfl_xor_sync(~0u, sT, 2); sP += __shfl_xor_sync(~0u, sP, 2);
            if ((lane & 3) == 0) {
                atomicAdd(&g_total[i0 + rl], sT);
                atomicAdd(&g_pos[i0 + rl], sP);
            }
        }
    }

    if (!diag) {
        #pragma unroll
        for (int x = 0; x < 16; x++) {
            float cT = colT[x], cP = colP[x];
            cT += __shfl_xor_sync(~0u, cT, 4);  cP += __shfl_xor_sync(~0u, cP, 4);
            cT += __shfl_xor_sync(~0u, cT, 8);  cP += __shfl_xor_sync(~0u, cP, 8);
            cT += __shfl_xor_sync(~0u, cT, 16); cP += __shfl_xor_sync(~0u, cP, 16);
            if (lane < 4) {
                int cl = wn * 64 + (x >> 1) * 8 + lane * 2 + (x & 1);
                atomicAdd(&s_colT[cl], cT);
                atomicAdd(&s_colP[cl], cP);
            }
        }
        __syncthreads();
        if (tid < TN) {
            atomicAdd(&g_total[j0 + tid], s_colT[tid]);
            atomicAdd(&g_pos[j0 + tid], s_colP[tid]);
        }
    }
}

// ---------------- final reduction: 32 blocks; last block finishes + restores state ----------------
__global__ void k_finalize(float* out) {
    int i = blockIdx.x * blockDim.x + threadIdx.x;
    float tot = g_total[i] + expf(INV_T);           // exact diagonal term
    float cnt = (float)(g_hist[g_lab[i]] - 1);
    float ps  = g_pos[i] / (cnt + 1e-9f);
    float s   = logf(ps / tot) * (-1.0f / (float)N_ROWS);
    #pragma unroll
    for (int o = 16; o; o >>= 1) s += __shfl_xor_sync(~0u, s, o);
    __shared__ float red[8];
    __shared__ unsigned s_rank;
    if ((threadIdx.x & 31) == 0) red[threadIdx.x >> 5] = s;
    __syncthreads();
    if (threadIdx.x < 8) {
        float v = red[threadIdx.x];
        #pragma unroll
        for (int o = 4; o; o >>= 1) v += __shfl_xor_sync(0xFF, v, o);
        if (threadIdx.x == 0) {
            g_part[blockIdx.x] = v;
            __threadfence();
            s_rank = atomicAdd(&g_done, 1u);
        }
    }
    __syncthreads();
    if (s_rank == 31u) {                 // last block: all partials + hist reads done
        __threadfence();
        if (threadIdx.x < 32) {
            float v = g_part[threadIdx.x];
            #pragma unroll
            for (int o = 16; o; o >>= 1) v += __shfl_xor_sync(~0u, v, o);
            if (threadIdx.x == 0) { out[0] = v; g_done = 0u; }
        }
        if (threadIdx.x < 128) g_hist[threadIdx.x] = 0;   // restore invariant for next call
    }
}

extern "C" void kernel_launch(void* const* d_in, const int* in_sizes, int n_in,
                              void* d_out, int out_size) {
    const float* hidden = (const float*)d_in[0];
    const void*  labels = d_in[1];

    cudaFuncSetAttribute(k_gemm_sym, cudaFuncAttributeMaxDynamicSharedMemorySize, SMEM_DYN);

    k_normalize<<<N_ROWS, 128>>>(hidden, labels);
    k_gemm_sym<<<NTILE, 256, SMEM_DYN>>>();
    k_finalize<<<32, 256>>>((float*)d_out);
}

// round 16
// speedup vs baseline: 1.2527x; 1.0021x over previous
#include <cuda_runtime.h>
#include <cuda_bf16.h>
#include <cstdint>

#define N_ROWS 8192
#define DIM    512
#define INV_T  (1.0f / 0.07f)

#define TM 128
#define TN 128
#define KC 64
#define NK (DIM / KC)            // 8 K-chunks
#define NTI (N_ROWS / TM)        // 64 tile-rows
#define NTILE (NTI * (NTI + 1) / 2)   // 2080 upper-triangle tiles
#define STAGE_BYTES ((TM + TN) * KC * 2)   // 32 KB
#define NSTAGE 3
#define SMEM_DYN (NSTAGE * STAGE_BYTES)    // 96 KB

// ---------------- scratch (no allocs allowed; zero-init at module load) ----------------
__device__ __align__(16) __nv_bfloat16 g_Hn[N_ROWS * DIM];   // normalized, bf16, row-major
__device__ float    g_total[N_ROWS];
__device__ float    g_pos[N_ROWS];
__device__ int      g_hist[128];      // zero at load; re-zeroed by k_finalize each call
__device__ int      g_lab[N_ROWS];
__device__ float    g_part[32];
__device__ unsigned g_done;           // zero at load; reset by k_finalize each call

// ---------------- L2-normalize: 1 warp/row, 8 rows/block, barrier-free ----------------
__global__ void __launch_bounds__(256) k_normalize(const float* __restrict__ hidden,
                                                   const void* labels) {
    const int w = threadIdx.x >> 5, lane = threadIdx.x & 31;
    const int row = blockIdx.x * 8 + w;

    if (lane == 0) {
        const int* l32 = (const int*)labels;
        int odd_nonzero = 0;
        #pragma unroll
        for (int q = 0; q < 16; q++)
            odd_nonzero += (l32[2 * q + 1] != 0);
        int l = (odd_nonzero == 0) ? (int)((const long long*)labels)[row]
                                   : l32[row];
        l &= 127;
        g_lab[row]   = l;
        g_total[row] = 0.f;
        g_pos[row]   = 0.f;
        atomicAdd(&g_hist[l], 1);
    }

    const float4* src = reinterpret_cast<const float4*>(hidden + (size_t)row * DIM);
    float4 v[4];
    float ss = 0.f;
    #pragma unroll
    for (int q = 0; q < 4; q++) {
        v[q] = src[lane + 32 * q];
        ss += v[q].x * v[q].x + v[q].y * v[q].y + v[q].z * v[q].z + v[q].w * v[q].w;
    }
    #pragma unroll
    for (int o = 16; o; o >>= 1) ss += __shfl_xor_sync(~0u, ss, o);
    const float inv = 1.0f / fmaxf(sqrtf(ss), 1e-12f);

    uint2* dst = reinterpret_cast<uint2*>((char*)g_Hn + (size_t)row * DIM * 2);
    #pragma unroll
    for (int q = 0; q < 4; q++) {
        __nv_bfloat162 p0 = __floats2bfloat162_rn(v[q].x * inv, v[q].y * inv);
        __nv_bfloat162 p1 = __floats2bfloat162_rn(v[q].z * inv, v[q].w * inv);
        uint2 pk;
        pk.x = *reinterpret_cast<uint32_t*>(&p0);
        pk.y = *reinterpret_cast<uint32_t*>(&p1);
        dst[lane + 32 * q] = pk;
    }
}

__device__ __forceinline__ uint32_t smem_u32(const void* p) {
    return (uint32_t)__cvta_generic_to_shared(p);
}
__device__ __forceinline__ void cp16(uint32_t dst, const void* src) {
    asm volatile("cp.async.cg.shared.global [%0], [%1], 16;" :: "r"(dst), "l"(src) : "memory");
}

// ---------------- symmetric-tile GEMM + fused epilogue (R11 measured-best, unchanged) ----------------
__global__ void __launch_bounds__(256, 2) k_gemm_sym() {
    extern __shared__ char smem[];
    __shared__ float s_colT[TN], s_colP[TN];
    __shared__ int   s_labI[TM], s_labJ[TN];

    const int tid  = threadIdx.x;
    const int lane = tid & 31, warp = tid >> 5;
    const int wm = warp >> 1, wn = warp & 1;   // 4x2 warps over 128x128

    // decode upper-triangle tile (ti <= tj); offset f(t) = t*(2*NTI+1-t)/2
    int bid = blockIdx.x;
    int ti = (int)((129.0f - sqrtf(129.0f * 129.0f - 8.0f * (float)bid)) * 0.5f);
    #define FOFF(t) ((t) * (2 * NTI + 1 - (t)) / 2)
    while (FOFF(ti + 1) <= bid) ti++;
    while (FOFF(ti) > bid) ti--;
    int tj = ti + (bid - FOFF(ti));
    const int i0 = ti * TM, j0 = tj * TN;
    const bool diag = (ti == tj);

    if (tid < TM) {
        s_labI[tid] = g_lab[i0 + tid];
        s_labJ[tid] = g_lab[j0 + tid];
        s_colT[tid] = 0.f; s_colP[tid] = 0.f;
    }

    // ---- cp.async tile loader: 128 rows x 8 x 16B per operand, XOR-swizzled ----
    auto load_stage = [&](int s, int k) {
        char* dA = smem + s * STAGE_BYTES;
        char* dB = dA + TM * KC * 2;
        const char* gA = (const char*)g_Hn + ((size_t)i0 * DIM + k * KC) * 2;
        const char* gB = (const char*)g_Hn + ((size_t)j0 * DIM + k * KC) * 2;
        #pragma unroll
        for (int u = 0; u < 4; u++) {
            int q = tid + u * 256;           // 0..1023
            int r = q >> 3, c = q & 7;
            uint32_t sw = (uint32_t)((c ^ (r & 7)) << 4);
            cp16(smem_u32(dA + r * 128 + sw), gA + (size_t)r * (DIM * 2) + c * 16);
            cp16(smem_u32(dB + r * 128 + sw), gB + (size_t)r * (DIM * 2) + c * 16);
        }
    };

    load_stage(0, 0);
    asm volatile("cp.async.commit_group;" ::: "memory");
    load_stage(1, 1);
    asm volatile("cp.async.commit_group;" ::: "memory");

    float acc[2][8][4];
    #pragma unroll
    for (int mi = 0; mi < 2; mi++)
        #pragma unroll
        for (int ni = 0; ni < 8; ni++)
            #pragma unroll
            for (int e = 0; e < 4; e++) acc[mi][ni][e] = 0.f;

    for (int k = 0; k < NK; k++) {
        __syncthreads();                          // all warps done with buf[(k+2)%3]
        if (k + 2 < NK) load_stage((k + 2) % NSTAGE, k + 2);
        asm volatile("cp.async.commit_group;" ::: "memory");
        asm volatile("cp.async.wait_group 2;" ::: "memory");
        __syncthreads();                          // stage k visible

        char* A = smem + (k % NSTAGE) * STAGE_BYTES;
        char* B = A + TM * KC * 2;
        #pragma unroll
        for (int ks = 0; ks < 4; ks++) {          // 4 x k16
            uint32_t a[2][4];
            #pragma unroll
            for (int mi = 0; mi < 2; mi++) {
                int r = wm * 32 + mi * 16 + (lane & 15);
                int ch = ks * 2 + (lane >> 4);
                uint32_t addr = smem_u32(A + r * 128 + ((ch ^ (r & 7)) << 4));
                asm volatile("ldmatrix.sync.aligned.m8n8.x4.shared.b16 {%0,%1,%2,%3}, [%4];\n"
                    : "=r"(a[mi][0]), "=r"(a[mi][1]), "=r"(a[mi][2]), "=r"(a[mi][3])
                    : "r"(addr));
            }
            uint32_t b[8][2];
            #pragma unroll
            for (int nb = 0; nb < 4; nb++) {
                int r = wn * 64 + nb * 16 + (lane >> 4) * 8 + (lane & 7);
                int ch = ks * 2 + ((lane >> 3) & 1);
                uint32_t addr = smem_u32(B + r * 128 + ((ch ^ (r & 7)) << 4));
                asm volatile("ldmatrix.sync.aligned.m8n8.x4.shared.b16 {%0,%1,%2,%3}, [%4];\n"
                    : "=r"(b[2 * nb][0]), "=r"(b[2 * nb][1]),
                      "=r"(b[2 * nb + 1][0]), "=r"(b[2 * nb + 1][1])
                    : "r"(addr));
            }
            #pragma unroll
            for (int mi = 0; mi < 2; mi++)
                #pragma unroll
                for (int ni = 0; ni < 8; ni++)
                    asm volatile(
                        "mma.sync.aligned.m16n8k16.row.col.f32.bf16.bf16.f32 "
                        "{%0,%1,%2,%3},{%4,%5,%6,%7},{%8,%9},{%0,%1,%2,%3};\n"
                        : "+f"(acc[mi][ni][0]), "+f"(acc[mi][ni][1]),
                          "+f"(acc[mi][ni][2]), "+f"(acc[mi][ni][3])
                        : "r"(a[mi][0]), "r"(a[mi][1]), "r"(a[mi][2]), "r"(a[mi][3]),
                          "r"(b[ni][0]), "r"(b[ni][1]));
        }
    }
    __syncthreads();

    // ---- epilogue: exp once, scatter to row sums (i) and column sums (j) ----
    float colT[16], colP[16];
    #pragma unroll
    for (int x = 0; x < 16; x++) { colT[x] = 0.f; colP[x] = 0.f; }

    #pragma unroll
    for (int mi = 0; mi < 2; mi++) {
        #pragma unroll
        for (int v = 0; v < 2; v++) {
            const int rl = wm * 32 + mi * 16 + (lane >> 2) + v * 8;
            const int li = s_labI[rl];
            float sT = 0.f, sP = 0.f;
            #pragma unroll
            for (int ni = 0; ni < 8; ni++) {
                #pragma unroll
                for (int e = 0; e < 2; e++) {
                    const int cl = wn * 64 + ni * 8 + (lane & 3) * 2 + e;
                    float ev = __expf(acc[mi][ni][v * 2 + e] * INV_T);
                    bool same = (s_labJ[cl] == li);
                    if (!(diag && rl == cl)) {
                        sT += ev;
                        if (same) sP += ev;
                        if (!diag) {
                            colT[ni * 2 + e] += ev;
                            if (same) colP[ni * 2 + e] += ev;
                        }
                    }
                }
            }
            sT += __shfl_xor_sync(~0u, sT, 1); sP += __shfl_xor_sync(~0u, sP, 1);
            sT += __shfl_xor_sync(~0u, sT, 2); sP += __shfl_xor_sync(~0u, sP, 2);
            if ((lane & 3) == 0) {
                atomicAdd(&g_total[i0 + rl], sT);
                atomicAdd(&g_pos[i0 + rl], sP);
            }
        }
    }

    if (!diag) {
        #pragma unroll
        for (int x = 0; x < 16; x++) {
            float cT = colT[x], cP = colP[x];
            cT += __shfl_xor_sync(~0u, cT, 4);  cP += __shfl_xor_sync(~0u, cP, 4);
            cT += __shfl_xor_sync(~0u, cT, 8);  cP += __shfl_xor_sync(~0u, cP, 8);
            cT += __shfl_xor_sync(~0u, cT, 16); cP += __shfl_xor_sync(~0u, cP, 16);
            if (lane < 4) {
                int cl = wn * 64 + (x >> 1) * 8 + lane * 2 + (x & 1);
                atomicAdd(&s_colT[cl], cT);
                atomicAdd(&s_colP[cl], cP);
            }
        }
        __syncthreads();
        if (tid < TN) {
            atomicAdd(&g_total[j0 + tid], s_colT[tid]);
            atomicAdd(&g_pos[j0 + tid], s_colP[tid]);
        }
    }
}

// ---------------- final reduction: 32 blocks; last block finishes + restores state ----------------
__global__ void k_finalize(float* out) {
    int i = blockIdx.x * blockDim.x + threadIdx.x;
    float tot = g_total[i] + expf(INV_T);           // exact diagonal term
    float cnt = (float)(g_hist[g_lab[i]] - 1);
    float ps  = g_pos[i] / (cnt + 1e-9f);
    float s   = logf(ps / tot) * (-1.0f / (float)N_ROWS);
    #pragma unroll
    for (int o = 16; o; o >>= 1) s += __shfl_xor_sync(~0u, s, o);
    __shared__ float red[8];
    __shared__ unsigned s_rank;
    if ((threadIdx.x & 31) == 0) red[threadIdx.x >> 5] = s;
    __syncthreads();
    if (threadIdx.x < 8) {
        float v = red[threadIdx.x];
        #pragma unroll
        for (int o = 4; o; o >>= 1) v += __shfl_xor_sync(0xFF, v, o);
        if (threadIdx.x == 0) {
            g_part[blockIdx.x] = v;
            __threadfence();
            s_rank = atomicAdd(&g_done, 1u);
        }
    }
    __syncthreads();
    if (s_rank == 31u) {                 // last block: all partials + hist reads done
        __threadfence();
        if (threadIdx.x < 32) {
            float v = g_part[threadIdx.x];
            #pragma unroll
            for (int o = 16; o; o >>= 1) v += __shfl_xor_sync(~0u, v, o);
            if (threadIdx.x == 0) { out[0] = v; g_done = 0u; }
        }
        if (threadIdx.x < 128) g_hist[threadIdx.x] = 0;   // restore invariant for next call
    }
}

extern "C" void kernel_launch(void* const* d_in, const int* in_sizes, int n_in,
                              void* d_out, int out_size) {
    const float* hidden = (const float*)d_in[0];
    const void*  labels = d_in[1];

    cudaFuncSetAttribute(k_gemm_sym, cudaFuncAttributeMaxDynamicSharedMemorySize, SMEM_DYN);

    k_normalize<<<N_ROWS / 8, 256>>>(hidden, labels);
    k_gemm_sym<<<NTILE, 256, SMEM_DYN>>>();
    k_finalize<<<32, 256>>>((float*)d_out);
}